// round 7
// baseline (speedup 1.0000x reference)
#include <cuda_runtime.h>
#include <math.h>

// ---------------------------------------------------------------------------
// TCVAE loss — single launch, fully-unrolled straight-line body.
//
// Algebra (ALPHA=BETA=GAMMA=1): pairwise logsumexp terms telescope away:
//   kl_loss = mean(log q(z|x)) - mean(log p(z))
// Remaining:
//   recon_loss = sum |x - recon| / (B*T)
//   kl_loss    = (1/B) * sum_{i,d} [ -0.5*((z-mu)^2*e^{-lv} + lv)
//                                    +0.5*( z^2*e^{-1}      + 1 ) ]
//
// 256 blocks x 256 threads = 65536 threads; n_bt4 = 262144 = 4*65536, so
// each thread owns exactly 4 recon4 + 4 x4 loads (8 independent LDG.128,
// front-batched, no loop) plus the KL triple for tid < 16384. One memory
// round-trip deep. Ticket finalize, idempotent across graph replays.
// ---------------------------------------------------------------------------

#define GRID_BLOCKS 256
#define BLOCK_THREADS 256
#define NTHREADS (GRID_BLOCKS * BLOCK_THREADS)   // 65536
#define NWARPS (BLOCK_THREADS / 32)              // 8

__device__ float2 g_partials[GRID_BLOCKS];
__device__ unsigned int g_ticket = 0;

__global__ void __launch_bounds__(BLOCK_THREADS) tcvae_fused_kernel(
    const float4* __restrict__ recon4,
    const float4* __restrict__ x4,
    const float4* __restrict__ mu4,
    const float4* __restrict__ lv4,
    const float4* __restrict__ z4,
    float* __restrict__ out,
    int n_bd4,                       // (B*D)/4 = 16384
    int n_bt, int batch)
{
    const float INV_E = 0.36787944117144233f;  // e^{-1}
    const int S = NTHREADS;          // 65536

    int tid = blockIdx.x * BLOCK_THREADS + threadIdx.x;

    // ---- front-batch ALL independent loads (MLP_p1 up to 11) ----
    float4 a0 = __ldcs(&recon4[tid]);
    float4 a1 = __ldcs(&recon4[tid + S]);
    float4 a2 = __ldcs(&recon4[tid + 2 * S]);
    float4 a3 = __ldcs(&recon4[tid + 3 * S]);
    float4 b0 = __ldcs(&x4[tid]);
    float4 b1 = __ldcs(&x4[tid + S]);
    float4 b2 = __ldcs(&x4[tid + 2 * S]);
    float4 b3 = __ldcs(&x4[tid + 3 * S]);

    bool has_kl = (tid < n_bd4);
    float4 m, l, s;
    if (has_kl) {
        m = __ldcs(&mu4[tid]);
        l = __ldcs(&lv4[tid]);
        s = __ldcs(&z4[tid]);
    }

    // ---- compute ----
    float racc = fabsf(b0.x - a0.x) + fabsf(b0.y - a0.y)
               + fabsf(b0.z - a0.z) + fabsf(b0.w - a0.w)
               + fabsf(b1.x - a1.x) + fabsf(b1.y - a1.y)
               + fabsf(b1.z - a1.z) + fabsf(b1.w - a1.w)
               + fabsf(b2.x - a2.x) + fabsf(b2.y - a2.y)
               + fabsf(b2.z - a2.z) + fabsf(b2.w - a2.w)
               + fabsf(b3.x - a3.x) + fabsf(b3.y - a3.y)
               + fabsf(b3.z - a3.z) + fabsf(b3.w - a3.w);

    float kacc = 0.0f;
    if (has_kl) {
        float t;
        t = s.x - m.x; kacc += -0.5f * (t*t*__expf(-l.x) + l.x) + 0.5f * (s.x*s.x*INV_E + 1.0f);
        t = s.y - m.y; kacc += -0.5f * (t*t*__expf(-l.y) + l.y) + 0.5f * (s.y*s.y*INV_E + 1.0f);
        t = s.z - m.z; kacc += -0.5f * (t*t*__expf(-l.z) + l.z) + 0.5f * (s.z*s.z*INV_E + 1.0f);
        t = s.w - m.w; kacc += -0.5f * (t*t*__expf(-l.w) + l.w) + 0.5f * (s.w*s.w*INV_E + 1.0f);
    }

    // ---- block reduction (8 warps) ----
    #pragma unroll
    for (int o = 16; o > 0; o >>= 1) {
        racc += __shfl_xor_sync(0xFFFFFFFFu, racc, o);
        kacc += __shfl_xor_sync(0xFFFFFFFFu, kacc, o);
    }

    __shared__ float sr[NWARPS];
    __shared__ float sk[NWARPS];
    int lane = threadIdx.x & 31;
    int warp = threadIdx.x >> 5;
    if (lane == 0) { sr[warp] = racc; sk[warp] = kacc; }
    __syncthreads();

    __shared__ bool is_last;
    if (warp == 0) {
        racc = (lane < NWARPS) ? sr[lane] : 0.0f;
        kacc = (lane < NWARPS) ? sk[lane] : 0.0f;
        #pragma unroll
        for (int o = 4; o > 0; o >>= 1) {
            racc += __shfl_xor_sync(0xFFFFFFFFu, racc, o);
            kacc += __shfl_xor_sync(0xFFFFFFFFu, kacc, o);
        }
        if (lane == 0) {
            g_partials[blockIdx.x] = make_float2(racc, kacc);
            // acq_rel: release orders the partial store before the ticket
            // bump; acquire covers the last block's partial reads.
            unsigned int t;
            asm volatile("atom.acq_rel.gpu.global.add.u32 %0, [%1], 1;"
                         : "=r"(t) : "l"(&g_ticket) : "memory");
            is_last = (t == (unsigned int)(GRID_BLOCKS - 1));
        }
    }
    __syncthreads();

    // ---- last-block finalize: 256 float2, exactly 1 per thread ----
    if (is_last) {
        float2 p = g_partials[threadIdx.x];
        float r = p.x, k = p.y;
        #pragma unroll
        for (int o = 16; o > 0; o >>= 1) {
            r += __shfl_xor_sync(0xFFFFFFFFu, r, o);
            k += __shfl_xor_sync(0xFFFFFFFFu, k, o);
        }
        __shared__ double dr[NWARPS];
        __shared__ double dk[NWARPS];
        if (lane == 0) { dr[warp] = (double)r; dk[warp] = (double)k; }
        __syncthreads();
        if (threadIdx.x == 0) {
            double rs = 0.0, ks = 0.0;
            #pragma unroll
            for (int w = 0; w < NWARPS; w++) { rs += dr[w]; ks += dk[w]; }
            float recon_loss = (float)(rs / (double)n_bt);
            float kl_loss    = (float)(ks / (double)batch);
            out[0] = recon_loss + kl_loss;
            out[1] = recon_loss;
            out[2] = kl_loss;
            g_ticket = 0;  // reset for next graph replay (idempotent)
        }
    }
}

extern "C" void kernel_launch(void* const* d_in, const int* in_sizes, int n_in,
                              void* d_out, int out_size) {
    const float* recon   = (const float*)d_in[0];  // [B, T]
    const float* x       = (const float*)d_in[1];  // [B, T]
    const float* mu      = (const float*)d_in[2];  // [B, D]
    const float* log_var = (const float*)d_in[3];  // [B, D]
    const float* z       = (const float*)d_in[4];  // [B, D]
    // d_in[5] = dataset_size: unused (telescoping cancellation).

    int n_bt = in_sizes[0];          // B*T = 1048576 (= 16 * NTHREADS floats)
    int n_bd = in_sizes[2];          // B*D = 65536
    const int batch = 2048;          // B

    tcvae_fused_kernel<<<GRID_BLOCKS, BLOCK_THREADS>>>(
        (const float4*)recon, (const float4*)x,
        (const float4*)mu, (const float4*)log_var, (const float4*)z,
        (float*)d_out, n_bd / 4, n_bt, batch);
}

// round 8
// speedup vs baseline: 1.4571x; 1.4571x over previous
#include <cuda_runtime.h>
#include <math.h>

// ---------------------------------------------------------------------------
// TCVAE loss — single launch, max-occupancy single wave.
//
// Algebra (ALPHA=BETA=GAMMA=1): pairwise logsumexp terms telescope away:
//   kl_loss = mean(log q(z|x)) - mean(log p(z))
// Remaining:
//   recon_loss = sum |x - recon| / (B*T)
//   kl_loss    = (1/B) * sum_{i,d} [ -0.5*((z-mu)^2*e^{-lv} + lv)
//                                    +0.5*( z^2*e^{-1}      + 1 ) ]
//
// 1024 blocks x 256 threads = 262144 threads = n_bt4 exactly: every thread
// owns ONE recon4 + ONE x4 load (straight line, uniform), KL triple for
// tid < 16384. ~55 warps/SM for latency hiding. Block partials go through
// deterministic fixed-point s64 red.add atomics (integer add commutes
// exactly -> bit-identical across orderings); last-ticket block reads the
// two scalars, writes the 3 outputs, resets state for the next graph replay.
// ---------------------------------------------------------------------------

#define GRID_BLOCKS 1024
#define BLOCK_THREADS 256
#define NWARPS (BLOCK_THREADS / 32)   // 8
#define FP_SCALE 1073741824.0f        // 2^30

__device__ unsigned long long g_racc_s64 = 0ULL;
__device__ unsigned long long g_kacc_s64 = 0ULL;
__device__ unsigned int g_ticket = 0;

__global__ void __launch_bounds__(BLOCK_THREADS) tcvae_fused_kernel(
    const float4* __restrict__ recon4,
    const float4* __restrict__ x4,
    const float4* __restrict__ mu4,
    const float4* __restrict__ lv4,
    const float4* __restrict__ z4,
    float* __restrict__ out,
    int n_bd4,                       // (B*D)/4 = 16384
    int n_bt, int batch)
{
    const float INV_E = 0.36787944117144233f;  // e^{-1}

    int tid = blockIdx.x * BLOCK_THREADS + threadIdx.x;

    // ---- loads: 1 recon4 + 1 x4 per thread (uniform), KL for low tids ----
    float4 a = __ldcs(&recon4[tid]);
    float4 b = __ldcs(&x4[tid]);

    bool has_kl = (tid < n_bd4);
    float4 m, l, s;
    if (has_kl) {
        m = __ldcs(&mu4[tid]);
        l = __ldcs(&lv4[tid]);
        s = __ldcs(&z4[tid]);
    }

    // ---- compute ----
    float racc = fabsf(b.x - a.x) + fabsf(b.y - a.y)
               + fabsf(b.z - a.z) + fabsf(b.w - a.w);

    float kacc = 0.0f;
    if (has_kl) {
        float t;
        t = s.x - m.x; kacc += -0.5f * (t*t*__expf(-l.x) + l.x) + 0.5f * (s.x*s.x*INV_E + 1.0f);
        t = s.y - m.y; kacc += -0.5f * (t*t*__expf(-l.y) + l.y) + 0.5f * (s.y*s.y*INV_E + 1.0f);
        t = s.z - m.z; kacc += -0.5f * (t*t*__expf(-l.z) + l.z) + 0.5f * (s.z*s.z*INV_E + 1.0f);
        t = s.w - m.w; kacc += -0.5f * (t*t*__expf(-l.w) + l.w) + 0.5f * (s.w*s.w*INV_E + 1.0f);
    }

    // ---- block reduction (8 warps) ----
    #pragma unroll
    for (int o = 16; o > 0; o >>= 1) {
        racc += __shfl_xor_sync(0xFFFFFFFFu, racc, o);
        kacc += __shfl_xor_sync(0xFFFFFFFFu, kacc, o);
    }

    __shared__ float sr[NWARPS];
    __shared__ float sk[NWARPS];
    int lane = threadIdx.x & 31;
    int warp = threadIdx.x >> 5;
    if (lane == 0) { sr[warp] = racc; sk[warp] = kacc; }
    __syncthreads();

    __shared__ bool is_last;
    if (warp == 0) {
        racc = (lane < NWARPS) ? sr[lane] : 0.0f;
        kacc = (lane < NWARPS) ? sk[lane] : 0.0f;
        #pragma unroll
        for (int o = 4; o > 0; o >>= 1) {
            racc += __shfl_xor_sync(0xFFFFFFFFu, racc, o);
            kacc += __shfl_xor_sync(0xFFFFFFFFu, kacc, o);
        }
        if (lane == 0) {
            // deterministic fixed-point accumulation (exact integer add)
            long long ri = __float2ll_rn(racc * FP_SCALE);
            long long ki = __float2ll_rn(kacc * FP_SCALE);
            atomicAdd(&g_racc_s64, (unsigned long long)ri);  // RED (no return use)
            atomicAdd(&g_kacc_s64, (unsigned long long)ki);
            // acq_rel ticket: release orders the two reds above; acquire
            // lets the last block read the completed accumulators.
            unsigned int t;
            asm volatile("atom.acq_rel.gpu.global.add.u32 %0, [%1], 1;"
                         : "=r"(t) : "l"(&g_ticket) : "memory");
            is_last = (t == (unsigned int)(GRID_BLOCKS - 1));
        }
    }
    __syncthreads();

    // ---- last-block finalize: read 2 scalars, write 3 floats, reset ----
    if (is_last && threadIdx.x == 0) {
        long long rs = (long long)g_racc_s64;
        long long ks = (long long)g_kacc_s64;
        double rsum = (double)rs / (double)FP_SCALE;
        double ksum = (double)ks / (double)FP_SCALE;
        float recon_loss = (float)(rsum / (double)n_bt);
        float kl_loss    = (float)(ksum / (double)batch);
        out[0] = recon_loss + kl_loss;
        out[1] = recon_loss;
        out[2] = kl_loss;
        // reset for next graph replay (idempotent)
        g_racc_s64 = 0ULL;
        g_kacc_s64 = 0ULL;
        __threadfence();   // order resets before the ticket release below
        g_ticket = 0;
    }
}

extern "C" void kernel_launch(void* const* d_in, const int* in_sizes, int n_in,
                              void* d_out, int out_size) {
    const float* recon   = (const float*)d_in[0];  // [B, T]
    const float* x       = (const float*)d_in[1];  // [B, T]
    const float* mu      = (const float*)d_in[2];  // [B, D]
    const float* log_var = (const float*)d_in[3];  // [B, D]
    const float* z       = (const float*)d_in[4];  // [B, D]
    // d_in[5] = dataset_size: unused (telescoping cancellation).

    int n_bt = in_sizes[0];          // B*T = 1048576 (= 4 * 262144 floats)
    int n_bd = in_sizes[2];          // B*D = 65536
    const int batch = 2048;          // B

    tcvae_fused_kernel<<<GRID_BLOCKS, BLOCK_THREADS>>>(
        (const float4*)recon, (const float4*)x,
        (const float4*)mu, (const float4*)log_var, (const float4*)z,
        (float*)d_out, n_bd / 4, n_bt, batch);
}

// round 9
// speedup vs baseline: 1.4676x; 1.0072x over previous
#include <cuda_runtime.h>
#include <math.h>

// ---------------------------------------------------------------------------
// TCVAE loss — single launch. R6 geometry (best measured: 512x256, stride
// 131072, unroll-2 recon) with: straight-line recon body, KL spread as
// scalars over half the threads (balanced straggler), and deterministic
// fixed-point s64 RED tail (no partial array, no gather).
//
// Algebra (ALPHA=BETA=GAMMA=1): pairwise logsumexp terms telescope away:
//   kl_loss = mean(log q(z|x)) - mean(log p(z))
// Remaining:
//   recon_loss = sum |x - recon| / (B*T)
//   kl_loss    = (1/B) * sum_{i,d} [ -0.5*((z-mu)^2*e^{-lv} + lv)
//                                    +0.5*( z^2*e^{-1}      + 1 ) ]
// ---------------------------------------------------------------------------

#define GRID_BLOCKS 512
#define BLOCK_THREADS 256
#define NTHREADS (GRID_BLOCKS * BLOCK_THREADS)   // 131072
#define NWARPS (BLOCK_THREADS / 32)              // 8
#define FP_SCALE 1073741824.0f                   // 2^30

__device__ unsigned long long g_racc_s64 = 0ULL;
__device__ unsigned long long g_kacc_s64 = 0ULL;
__device__ unsigned int g_ticket = 0;

__global__ void __launch_bounds__(BLOCK_THREADS) tcvae_fused_kernel(
    const float4* __restrict__ recon4,
    const float4* __restrict__ x4,
    const float* __restrict__ mu,
    const float* __restrict__ lv,
    const float* __restrict__ z,
    float* __restrict__ out,
    int n_bd,                        // B*D = 65536
    int n_bt, int batch)
{
    const float INV_E = 0.36787944117144233f;  // e^{-1}

    int tid = blockIdx.x * BLOCK_THREADS + threadIdx.x;

    // ---- front-batch all independent loads ----
    // recon: exactly 2 float4 pairs per thread (262144 = 2 * 131072)
    float4 a0 = __ldcs(&recon4[tid]);
    float4 a1 = __ldcs(&recon4[tid + NTHREADS]);
    float4 b0 = __ldcs(&x4[tid]);
    float4 b1 = __ldcs(&x4[tid + NTHREADS]);

    // KL: one SCALAR element for tid < 65536 (balanced: 12B + 1 MUFU extra)
    bool has_kl = (tid < n_bd);
    float mm = 0.0f, ll = 0.0f, ss = 0.0f;
    if (has_kl) {
        mm = __ldcs(&mu[tid]);
        ll = __ldcs(&lv[tid]);
        ss = __ldcs(&z[tid]);
    }

    // ---- compute ----
    float racc = fabsf(b0.x - a0.x) + fabsf(b0.y - a0.y)
               + fabsf(b0.z - a0.z) + fabsf(b0.w - a0.w)
               + fabsf(b1.x - a1.x) + fabsf(b1.y - a1.y)
               + fabsf(b1.z - a1.z) + fabsf(b1.w - a1.w);

    float kacc = 0.0f;
    if (has_kl) {
        float t = ss - mm;
        kacc = -0.5f * (t * t * __expf(-ll) + ll)
             + 0.5f * (ss * ss * INV_E + 1.0f);
    }

    // ---- block reduction (8 warps) ----
    #pragma unroll
    for (int o = 16; o > 0; o >>= 1) {
        racc += __shfl_xor_sync(0xFFFFFFFFu, racc, o);
        kacc += __shfl_xor_sync(0xFFFFFFFFu, kacc, o);
    }

    __shared__ float sr[NWARPS];
    __shared__ float sk[NWARPS];
    int lane = threadIdx.x & 31;
    int warp = threadIdx.x >> 5;
    if (lane == 0) { sr[warp] = racc; sk[warp] = kacc; }
    __syncthreads();

    __shared__ bool is_last;
    if (warp == 0) {
        racc = (lane < NWARPS) ? sr[lane] : 0.0f;
        kacc = (lane < NWARPS) ? sk[lane] : 0.0f;
        #pragma unroll
        for (int o = 4; o > 0; o >>= 1) {
            racc += __shfl_xor_sync(0xFFFFFFFFu, racc, o);
            kacc += __shfl_xor_sync(0xFFFFFFFFu, kacc, o);
        }
        if (lane == 0) {
            // deterministic fixed-point accumulation (exact integer add,
            // order-independent => bit-identical across replays)
            long long ri = __float2ll_rn(racc * FP_SCALE);
            long long ki = __float2ll_rn(kacc * FP_SCALE);
            atomicAdd(&g_racc_s64, (unsigned long long)ri);  // RED
            atomicAdd(&g_kacc_s64, (unsigned long long)ki);  // RED
            // acq_rel ticket: release orders the REDs; acquire covers the
            // last block's scalar reads.
            unsigned int t;
            asm volatile("atom.acq_rel.gpu.global.add.u32 %0, [%1], 1;"
                         : "=r"(t) : "l"(&g_ticket) : "memory");
            is_last = (t == (unsigned int)(GRID_BLOCKS - 1));
        }
    }
    __syncthreads();

    // ---- last-block finalize: 2 scalar reads, 3 writes, reset ----
    if (is_last && threadIdx.x == 0) {
        long long rs = (long long)g_racc_s64;
        long long ks = (long long)g_kacc_s64;
        double rsum = (double)rs / (double)FP_SCALE;
        double ksum = (double)ks / (double)FP_SCALE;
        float recon_loss = (float)(rsum / (double)n_bt);
        float kl_loss    = (float)(ksum / (double)batch);
        out[0] = recon_loss + kl_loss;
        out[1] = recon_loss;
        out[2] = kl_loss;
        // reset for next graph replay (idempotent)
        g_racc_s64 = 0ULL;
        g_kacc_s64 = 0ULL;
        __threadfence();   // order resets before ticket release
        g_ticket = 0;
    }
}

extern "C" void kernel_launch(void* const* d_in, const int* in_sizes, int n_in,
                              void* d_out, int out_size) {
    const float* recon   = (const float*)d_in[0];  // [B, T]
    const float* x       = (const float*)d_in[1];  // [B, T]
    const float* mu      = (const float*)d_in[2];  // [B, D]
    const float* log_var = (const float*)d_in[3];  // [B, D]
    const float* z       = (const float*)d_in[4];  // [B, D]
    // d_in[5] = dataset_size: unused (telescoping cancellation).

    int n_bt = in_sizes[0];          // B*T = 1048576
    int n_bd = in_sizes[2];          // B*D = 65536
    const int batch = 2048;          // B

    tcvae_fused_kernel<<<GRID_BLOCKS, BLOCK_THREADS>>>(
        (const float4*)recon, (const float4*)x,
        mu, log_var, z,
        (float*)d_out, n_bd, n_bt, batch);
}